// round 1
// baseline (speedup 1.0000x reference)
#include <cuda_runtime.h>

// Problem constants
#define Bc 64
#define Kc 5
#define Hc 320
#define Wc 320
#define Nc (Hc * Wc)        // 102400 pixels per (b,k)
#define NGc (Nc / 4)        // 25600 float4 groups
#define BPB 25              // blocks per batch (25*256*4 = 25600 exactly, 4 iters/thread)
#define THREADS 256

// Per-block partial sums: [b][block][32] (26 used). Fully overwritten every launch.
__device__ float g_scratch[Bc * BPB * 32];

// Per-element update. Computes sigmoid and softplus with FMA-only approximations
// (no MUFU in the hot loop — MUFU throughput would be ~28x the memory floor).
__device__ __forceinline__ void elem(float x, float fg,
                                     float& S, float& I, float& C,
                                     float& XS, float& XF)
{
    // e = exp(-|x|), via exp2 with magic-number round + deg-5 poly (rel err ~3e-6)
    float t = fminf(fabsf(x), 20.0f);
    float y = -1.4426950408889634f * t;          // y in [-28.9, 0]
    float r = y + 12582912.0f;                   // round-to-nearest int in mantissa
    float nf = r - 12582912.0f;                  // exact rounded value
    float f = y - nf;                            // f in [-0.5, 0.5]
    float p2 = 0.0013333558f;
    p2 = fmaf(p2, f, 0.0096181291f);
    p2 = fmaf(p2, f, 0.0555041087f);
    p2 = fmaf(p2, f, 0.2402265069f);
    p2 = fmaf(p2, f, 0.6931471806f);
    p2 = fmaf(p2, f, 1.0f);
    int ni = __float_as_int(r) - 0x4B400000;     // = round(y), in [-29, 0]
    float e = __int_as_float(__float_as_int(p2) + (ni << 23));   // exp(-t) in (0,1]

    // softplus(-t) = log1p(e): Taylor about e=0.5, g=(e-0.5)/1.5, |g|<=1/3.
    // Truncation error <= (1/3)^10/10 * 1.5 ~ 2.5e-6 abs; exact 0 at e->0 limit.
    float g = fmaf(e, 0.6666666865f, -0.3333333433f);
    float s = 0.11111111f;
    s = fmaf(s, g, -0.125f);
    s = fmaf(s, g, 0.14285715f);
    s = fmaf(s, g, -0.16666667f);
    s = fmaf(s, g, 0.2f);
    s = fmaf(s, g, -0.25f);
    s = fmaf(s, g, 0.33333334f);
    s = fmaf(s, g, -0.5f);
    s = fmaf(s, g, 1.0f);
    float sp = fmaf(s, g, 0.40546510810816f);    // + ln(1.5)

    // q = 1/(1+e) = sigmoid(|x|): NR-division seed 24/17 - 8/17*u + 2 Newton steps
    // (rel err ~1e-5; only feeds the discrete argmin decision, where per-element
    //  biases cancel across k).
    float u = 1.0f + e;
    float rc = fmaf(u, -0.47058824f, 1.4117647f);
    rc = rc * fmaf(-u, rc, 2.0f);
    rc = rc * fmaf(-u, rc, 2.0f);
    float p = (x >= 0.0f) ? rc : (1.0f - rc);    // sigmoid(x)

    C += fmaxf(x, 0.0f) + sp;                    // alignment-independent BCE part
    S += p;
    I = fmaf(p, fg, I);
    XS += x;
    XF = fmaf(x, fg, XF);
}

__global__ __launch_bounds__(THREADS)
void hung_main(const float* __restrict__ slot, const float* __restrict__ tgt)
{
    const int b = blockIdx.y;
    const int tid = threadIdx.x;

    float acc[26];
#pragma unroll
    for (int i = 0; i < 26; i++) acc[i] = 0.0f;

    const float4* tg4 = reinterpret_cast<const float4*>(tgt) + (size_t)b * NGc;
    const float4* sl4 = reinterpret_cast<const float4*>(slot) + (size_t)b * Kc * NGc;

    for (int g = blockIdx.x * THREADS + tid; g < NGc; g += gridDim.x * THREADS) {
        const float4 fg = __ldg(&tg4[g]);
        acc[25] += (fg.x + fg.y) + (fg.z + fg.w);
#pragma unroll
        for (int k = 0; k < Kc; k++) {
            const float4 xv = __ldg(&sl4[(size_t)k * NGc + g]);
            elem(xv.x, fg.x, acc[k*5+0], acc[k*5+1], acc[k*5+2], acc[k*5+3], acc[k*5+4]);
            elem(xv.y, fg.y, acc[k*5+0], acc[k*5+1], acc[k*5+2], acc[k*5+3], acc[k*5+4]);
            elem(xv.z, fg.z, acc[k*5+0], acc[k*5+1], acc[k*5+2], acc[k*5+3], acc[k*5+4]);
            elem(xv.w, fg.w, acc[k*5+0], acc[k*5+1], acc[k*5+2], acc[k*5+3], acc[k*5+4]);
        }
    }

    // Block reduction: warp shuffle then cross-warp via shared (deterministic).
#pragma unroll
    for (int i = 0; i < 26; i++) {
        float v = acc[i];
#pragma unroll
        for (int o = 16; o > 0; o >>= 1) v += __shfl_xor_sync(0xffffffffu, v, o);
        acc[i] = v;
    }
    __shared__ float sm[THREADS / 32][26];
    const int warp = tid >> 5, lane = tid & 31;
    if (lane == 0) {
#pragma unroll
        for (int i = 0; i < 26; i++) sm[warp][i] = acc[i];
    }
    __syncthreads();
    if (tid < 26) {
        float s = 0.0f;
#pragma unroll
        for (int w = 0; w < THREADS / 32; w++) s += sm[w][tid];
        g_scratch[((size_t)b * gridDim.x + blockIdx.x) * 32 + tid] = s;
    }
}

// One block of 64 threads (one per batch): sum partials, pick k0 (the slot
// assigned to the fg column -- the 120-perm argmin reduces to this), assemble loss.
__global__ void hung_final(float* __restrict__ out)
{
    __shared__ float red[Bc];
    const int b = threadIdx.x;

    float a[26];
#pragma unroll
    for (int i = 0; i < 26; i++) a[i] = 0.0f;
    for (int j = 0; j < BPB; j++) {
        const float* p = &g_scratch[((size_t)b * BPB + j) * 32];
#pragma unroll
        for (int i = 0; i < 26; i++) a[i] += p[i];
    }

    const float Tfg = a[25];
    const float Tbg = (float)Nc - Tfg;
    float sumC = 0.0f, sumXS = 0.0f, sumXF = 0.0f;
    float best = 3.4e38f, selXS = 0.0f, selXF = 0.0f;
#pragma unroll
    for (int k = 0; k < Kc; k++) {
        const float S  = a[k*5+0];
        const float I  = a[k*5+1];
        const float Cv = a[k*5+2];
        const float XS = a[k*5+3];
        const float XF = a[k*5+4];
        const float Ib = S - I;
        const float cfg = 1.0f - I  / (S + Tfg - I  + 1e-6f);
        const float cbg = 1.0f - Ib / (S + Tbg - Ib + 1e-6f);
        const float score = cfg - cbg;   // perm cost differs only by this term
        if (score < best) { best = score; selXS = XS; selXF = XF; }  // ties -> smallest k (lexicographic PERMS)
        sumC += Cv; sumXS += XS; sumXF += XF;
    }
    // loss_b = sum_k C_k - [XF_k0 + sum_{k!=k0}(XS_k - XF_k)]
    const float loss_b = sumC - sumXS + sumXF + selXS - 2.0f * selXF;

    red[b] = loss_b;
    __syncthreads();
    if (b == 0) {
        float tot = 0.0f;
        for (int i = 0; i < Bc; i++) tot += red[i];
        out[0] = tot * (1.0f / ((float)Bc * (float)Kc * (float)Nc));
    }
}

extern "C" void kernel_launch(void* const* d_in, const int* in_sizes, int n_in,
                              void* d_out, int out_size)
{
    // metadata order: fg_logits (unused by reference), slot_logits, target
    const float* slot = (const float*)d_in[1];
    const float* tgt  = (const float*)d_in[2];
    float* out = (float*)d_out;

    dim3 grid(BPB, Bc);
    hung_main<<<grid, THREADS>>>(slot, tgt);
    hung_final<<<1, Bc>>>(out);
}

// round 2
// speedup vs baseline: 2.2333x; 2.2333x over previous
#include <cuda_runtime.h>

// Problem constants
#define Bc 64
#define Kc 5
#define Hc 320
#define Wc 320
#define Nc (Hc * Wc)        // 102400 pixels per (b,k)
#define NGc (Nc / 4)        // 25600 float4 groups
#define BPB 25              // blocks per batch (25*256*4 = 25600 exactly)
#define THREADS 256

// Per-block partial sums: [b][block][32] (cols 0..25 used; 26..31 never touched).
__device__ float g_scratch[Bc * BPB * 32];

// Per-element update. MUFU-based: EX2 + LG2 + RCP per element is only ~23us of
// MUFU-pipe time chip-wide (3.07M warp-instrs / 74 per cyc), below the ~26us
// HBM floor, and it frees the fma pipe (which was the binding pipe before).
__device__ __forceinline__ void elem(float x, float fg,
                                     float& S, float& I, float& C,
                                     float& XS, float& XF)
{
    const float t  = fabsf(x);
    const float e  = __expf(-t);                 // FMUL + MUFU.EX2
    const float u  = 1.0f + e;
    const float rc = __fdividef(1.0f, u);        // MUFU.RCP (+mul)
    const float p  = (x >= 0.0f) ? rc : (1.0f - rc);   // sigmoid(x)
    const float sp = __logf(u);                  // log1p(e) = MUFU.LG2 + FMUL

    C += fmaxf(x, 0.0f) + sp;                    // alignment-independent BCE part
    S += p;
    I  = fmaf(p, fg, I);
    XS += x;
    XF = fmaf(x, fg, XF);
}

__global__ __launch_bounds__(THREADS)
void hung_main(const float* __restrict__ slot, const float* __restrict__ tgt)
{
    const int b = blockIdx.y;
    const int tid = threadIdx.x;

    float acc[26];
#pragma unroll
    for (int i = 0; i < 26; i++) acc[i] = 0.0f;

    const float4* tg4 = reinterpret_cast<const float4*>(tgt) + (size_t)b * NGc;
    const float4* sl4 = reinterpret_cast<const float4*>(slot) + (size_t)b * Kc * NGc;

    for (int g = blockIdx.x * THREADS + tid; g < NGc; g += gridDim.x * THREADS) {
        const float4 fg = __ldg(&tg4[g]);
        acc[25] += (fg.x + fg.y) + (fg.z + fg.w);
#pragma unroll
        for (int k = 0; k < Kc; k++) {
            const float4 xv = __ldg(&sl4[(size_t)k * NGc + g]);
            elem(xv.x, fg.x, acc[k*5+0], acc[k*5+1], acc[k*5+2], acc[k*5+3], acc[k*5+4]);
            elem(xv.y, fg.y, acc[k*5+0], acc[k*5+1], acc[k*5+2], acc[k*5+3], acc[k*5+4]);
            elem(xv.z, fg.z, acc[k*5+0], acc[k*5+1], acc[k*5+2], acc[k*5+3], acc[k*5+4]);
            elem(xv.w, fg.w, acc[k*5+0], acc[k*5+1], acc[k*5+2], acc[k*5+3], acc[k*5+4]);
        }
    }

    // Block reduction: warp shuffle then cross-warp via shared (deterministic).
#pragma unroll
    for (int i = 0; i < 26; i++) {
        float v = acc[i];
#pragma unroll
        for (int o = 16; o > 0; o >>= 1) v += __shfl_xor_sync(0xffffffffu, v, o);
        acc[i] = v;
    }
    __shared__ float sm[THREADS / 32][26];
    const int warp = tid >> 5, lane = tid & 31;
    if (lane == 0) {
#pragma unroll
        for (int i = 0; i < 26; i++) sm[warp][i] = acc[i];
    }
    __syncthreads();
    if (tid < 26) {
        float s = 0.0f;
#pragma unroll
        for (int w = 0; w < THREADS / 32; w++) s += sm[w][tid];
        g_scratch[((size_t)b * gridDim.x + blockIdx.x) * 32 + tid] = s;
    }
}

// Parallel finalize: 1 block x 1024 threads.
// Phase 1: 2048 (b,col) targets, each thread reduces BPB=25 partials with
// coalesced, MLP-rich loads (previous version: 2 warps, serialized latency, 43us).
// Phase 2: 64 threads do the per-batch k0 selection + loss assembly.
__global__ __launch_bounds__(1024)
void hung_final(float* __restrict__ out)
{
    __shared__ float sa[Bc][32];
    __shared__ float red[Bc];
    const int tid = threadIdx.x;

#pragma unroll
    for (int s = tid; s < Bc * 32; s += 1024) {
        const int b = s >> 5, i = s & 31;
        float v = 0.0f;
#pragma unroll
        for (int j = 0; j < BPB; j++)
            v += g_scratch[((size_t)b * BPB + j) * 32 + i];
        sa[b][i] = v;
    }
    __syncthreads();

    if (tid < Bc) {
        const float* a = sa[tid];
        const float Tfg = a[25];
        const float Tbg = (float)Nc - Tfg;
        float sumC = 0.0f, sumXS = 0.0f, sumXF = 0.0f;
        float best = 3.4e38f, selXS = 0.0f, selXF = 0.0f;
#pragma unroll
        for (int k = 0; k < Kc; k++) {
            const float S  = a[k*5+0];
            const float I  = a[k*5+1];
            const float Cv = a[k*5+2];
            const float XS = a[k*5+3];
            const float XF = a[k*5+4];
            const float Ib = S - I;
            const float cfg = 1.0f - I  / (S + Tfg - I  + 1e-6f);
            const float cbg = 1.0f - Ib / (S + Tbg - Ib + 1e-6f);
            const float score = cfg - cbg;   // perm cost differs only by this term
            if (score < best) { best = score; selXS = XS; selXF = XF; }  // ties -> smallest k
            sumC += Cv; sumXS += XS; sumXF += XF;
        }
        // loss_b = sum_k C_k - [XF_k0 + sum_{k!=k0}(XS_k - XF_k)]
        red[tid] = sumC - sumXS + sumXF + selXS - 2.0f * selXF;
    }
    __syncthreads();
    if (tid == 0) {
        float tot = 0.0f;
#pragma unroll
        for (int i = 0; i < Bc; i++) tot += red[i];
        out[0] = tot * (1.0f / ((float)Bc * (float)Kc * (float)Nc));
    }
}

extern "C" void kernel_launch(void* const* d_in, const int* in_sizes, int n_in,
                              void* d_out, int out_size)
{
    // metadata order: fg_logits (unused by reference), slot_logits, target
    const float* slot = (const float*)d_in[1];
    const float* tgt  = (const float*)d_in[2];
    float* out = (float*)d_out;

    dim3 grid(BPB, Bc);
    hung_main<<<grid, THREADS>>>(slot, tgt);
    hung_final<<<1, 1024>>>(out);
}